// round 9
// baseline (speedup 1.0000x reference)
#include <cuda_runtime.h>
#include <math.h>

#define BATCH 4096
#define NNEG 64
#define DIM 128
#define HID 512
#define HALF 256
#define MARGINF 24.0f
#define MROWS 32

// Scratch (__device__ globals; overwritten every replay, no zeroing needed).
__device__ float g_part[2][BATCH];   // per-half logit partials
__device__ float g_dpos[BATCH];
__device__ float g_negsp[BATCH];

__device__ __forceinline__ float warp_sum(float v) {
#pragma unroll
    for (int o = 16; o; o >>= 1) v += __shfl_xor_sync(0xffffffffu, v, o);
    return v;
}

// stable softplus(z) = max(z,0) + log1p(exp(-|z|));  -log_sigmoid(x) = softplus(-x)
__device__ __forceinline__ float softplusf(float z) {
    return fmaxf(z, 0.f) + log1pf(expf(-fabsf(z)));
}

// ---------------------------------------------------------------------------
// MLP / positive kernel, hidden-split. 256 blocks (128 row-tiles x 2 halves)
// x 256 threads. Thread owns ONE hidden column of its half across 32 rows
// (acc[32] scalar FFMA = proven R1 instruction mix). 2 blocks/SM -> 16 warps
// for latency cover; per-block W1 read = 128 KB so total W1 LTS traffic is
// unchanged (32 MB).
// ---------------------------------------------------------------------------
__global__ __launch_bounds__(256, 2) void mlp_pos_kernel(
    const int* __restrict__ pos, const float* __restrict__ ent,
    const float* __restrict__ rel, const float* __restrict__ W1,
    const float* __restrict__ b1, const float* __restrict__ W2,
    float* __restrict__ out)
{
    __shared__ float shA[DIM][36];      // diff tile [k][row], pitch 36 (16B-aligned)
    __shared__ int   sh_idx[MROWS][3];
    __shared__ float sh_part[8][MROWS];

    const int tid  = threadIdx.x;
    const int lane = tid & 31;
    const int wid  = tid >> 5;          // 0..7
    const int tile = blockIdx.x >> 1;
    const int half = blockIdx.x & 1;
    const int row0 = tile * MROWS;

    if (blockIdx.x == 0 && tid == 0) out[0] = 0.f;

    if (tid < MROWS * 3)
        sh_idx[tid / 3][tid % 3] = pos[(row0 + tid / 3) * 3 + (tid % 3)];
    __syncthreads();

    // gather + diff: consecutive tid -> consecutive k (coalesced 512B per row)
#pragma unroll
    for (int s = tid; s < MROWS * DIM; s += 256) {
        int row = s >> 7, k = s & 127;
        size_t h = (size_t)sh_idx[row][0];
        int    r = sh_idx[row][1];
        size_t t = (size_t)sh_idx[row][2];
        shA[k][row] = ent[h * DIM + k] + rel[(size_t)r * DIM + k] - ent[t * DIM + k];
    }
    __syncthreads();

    // d_pos (half 0 only): warp wid -> rows wid*4..+3
    if (half == 0) {
#pragma unroll
        for (int rr = 0; rr < 4; rr++) {
            int row = wid * 4 + rr;
            float s = 0.f;
#pragma unroll
            for (int kk = 0; kk < 4; kk++) s += fabsf(shA[lane + kk * 32][row]);
            s = warp_sum(s);
            if (lane == 0) g_dpos[row0 + row] = s;
        }
    }

    // GEMM: thread owns column j = half*HALF + tid, 32 row accumulators
    const int j = half * HALF + tid;
    float acc[MROWS];
#pragma unroll
    for (int r = 0; r < MROWS; r++) acc[r] = 0.f;

#pragma unroll 4
    for (int k = 0; k < DIM; k++) {
        float w = __ldg(&W1[(size_t)k * HID + j]);       // coalesced LDG.32
#pragma unroll
        for (int q = 0; q < MROWS / 4; q++) {
            float4 d4 = *(const float4*)&shA[k][q * 4];  // broadcast LDS.128
            acc[q * 4 + 0] = fmaf(d4.x, w, acc[q * 4 + 0]);
            acc[q * 4 + 1] = fmaf(d4.y, w, acc[q * 4 + 1]);
            acc[q * 4 + 2] = fmaf(d4.z, w, acc[q * 4 + 2]);
            acc[q * 4 + 3] = fmaf(d4.w, w, acc[q * 4 + 3]);
        }
    }

    const float bj = __ldg(&b1[j]), w2 = __ldg(&W2[j]);
#pragma unroll
    for (int r = 0; r < MROWS; r++) acc[r] = fmaxf(acc[r] + bj, 0.f) * w2;

    // reduce 256 threads -> half-partial per row
#pragma unroll
    for (int r = 0; r < MROWS; r++) {
        float v = warp_sum(acc[r]);
        if (lane == 0) sh_part[wid][r] = v;
    }
    __syncthreads();
    if (tid < MROWS) {
        float s = 0.f;
#pragma unroll
        for (int w = 0; w < 8; w++) s += sh_part[w][tid];
        g_part[half][row0 + tid] = s;
    }
}

// ---------------------------------------------------------------------------
// Negative kernel (R8-proven). One block per batch row, 8 warps; warp owns 8
// contiguous negs; 24 indices via one coalesced LDG + shuffle; 2 negs in
// flight per step (6 outstanding 512B gathers).
// ---------------------------------------------------------------------------
__global__ __launch_bounds__(256, 8) void neg_kernel(
    const int* __restrict__ negt, const float* __restrict__ ent,
    const float* __restrict__ rel)
{
    const int b    = blockIdx.x;
    const int lane = threadIdx.x & 31;
    const int wid  = threadIdx.x >> 5;
    __shared__ float sh[8];

    // one coalesced load of this warp's 24 indices (negs wid*8 .. wid*8+7)
    int myidx = 0;
    if (lane < 24)
        myidx = __ldg(negt + (b * NNEG + wid * 8) * 3 + lane);

    float local = 0.f;
#pragma unroll
    for (int u = 0; u < 4; u++) {
        const int i0 = u * 2, i1 = u * 2 + 1;
        int h0 = __shfl_sync(0xffffffffu, myidx, i0 * 3);
        int r0 = __shfl_sync(0xffffffffu, myidx, i0 * 3 + 1);
        int t0 = __shfl_sync(0xffffffffu, myidx, i0 * 3 + 2);
        int h1 = __shfl_sync(0xffffffffu, myidx, i1 * 3);
        int r1 = __shfl_sync(0xffffffffu, myidx, i1 * 3 + 1);
        int t1 = __shfl_sync(0xffffffffu, myidx, i1 * 3 + 2);

        float4 a0 = __ldg((const float4*)(ent + (size_t)h0 * DIM) + lane);
        float4 c0 = __ldg((const float4*)(ent + (size_t)t0 * DIM) + lane);
        float4 a1 = __ldg((const float4*)(ent + (size_t)h1 * DIM) + lane);
        float4 c1 = __ldg((const float4*)(ent + (size_t)t1 * DIM) + lane);
        float4 q0 = __ldg((const float4*)(rel + (size_t)r0 * DIM) + lane);
        float4 q1 = __ldg((const float4*)(rel + (size_t)r1 * DIM) + lane);

        float s0 = fabsf(a0.x + q0.x - c0.x) + fabsf(a0.y + q0.y - c0.y)
                 + fabsf(a0.z + q0.z - c0.z) + fabsf(a0.w + q0.w - c0.w);
        float s1 = fabsf(a1.x + q1.x - c1.x) + fabsf(a1.y + q1.y - c1.y)
                 + fabsf(a1.z + q1.z - c1.z) + fabsf(a1.w + q1.w - c1.w);
        s0 = warp_sum(s0);
        s1 = warp_sum(s1);
        if (lane == 0)
            local += softplusf(s0 - MARGINF) + softplusf(s1 - MARGINF);
    }
    if (lane == 0) sh[wid] = local;
    __syncthreads();
    if (threadIdx.x == 0) {
        float t = 0.f;
#pragma unroll
        for (int w = 0; w < 8; w++) t += sh[w];
        g_negsp[b] = t;
    }
}

// ---------------------------------------------------------------------------
// Final combine: 8 blocks x 512 threads, one row/thread; combine half
// partials -> conf, loss terms, double block-reduce, atomicAdd into out[0].
// ---------------------------------------------------------------------------
__global__ __launch_bounds__(512, 2) void final_kernel(
    const float* __restrict__ b2, float* __restrict__ out)
{
    __shared__ double sh[16];
    const int tid = threadIdx.x;
    const int i = blockIdx.x * 512 + tid;

    float logit = b2[0] + g_part[0][i] + g_part[1][i];
    float conf  = 1.f / (1.f + expf(-logit));
    float pt = softplusf(g_dpos[i] - MARGINF);       // -log_sigmoid(M - d_pos)
    float nt = -g_negsp[i] * (1.f / NNEG);           // mean log_sigmoid(M - d_neg)
    double local = (double)(conf * (pt + nt));

#pragma unroll
    for (int o = 16; o; o >>= 1) local += __shfl_xor_sync(0xffffffffu, local, o);
    const int lane = tid & 31, wid = tid >> 5;
    if (lane == 0) sh[wid] = local;
    __syncthreads();
    if (tid < 16) {
        double v = sh[tid];
#pragma unroll
        for (int o = 8; o; o >>= 1) v += __shfl_xor_sync(0x0000ffffu, v, o);
        if (tid == 0) atomicAdd(out, (float)v);
    }
}

// ---------------------------------------------------------------------------
// Fork/join overlap: small-footprint mlp on side stream hides under the
// LTS/DRAM-bound neg kernel on the capture stream.
// ---------------------------------------------------------------------------
extern "C" void kernel_launch(void* const* d_in, const int* in_sizes, int n_in,
                              void* d_out, int out_size)
{
    static cudaStream_t s2 = nullptr;
    static cudaEvent_t evFork = nullptr, evJoin = nullptr;
    if (s2 == nullptr) {
        cudaStreamCreateWithFlags(&s2, cudaStreamNonBlocking);
        cudaEventCreateWithFlags(&evFork, cudaEventDisableTiming);
        cudaEventCreateWithFlags(&evJoin, cudaEventDisableTiming);
    }

    const int* pos = (const int*)d_in[0];
    const int* neg = (const int*)d_in[1];
    const int o = (n_in >= 9) ? 1 : 0;   // negative_sample_size scalar slot
    const float* ent = (const float*)d_in[2 + o];
    const float* rel = (const float*)d_in[3 + o];
    const float* W1  = (const float*)d_in[4 + o];
    const float* b1  = (const float*)d_in[5 + o];
    const float* W2  = (const float*)d_in[6 + o];
    const float* b2  = (const float*)d_in[7 + o];
    float* out = (float*)d_out;

    // fork: side stream inherits capture via event wait
    cudaEventRecord(evFork, 0);
    cudaStreamWaitEvent(s2, evFork, 0);

    mlp_pos_kernel<<<256, 256, 0, s2>>>(pos, ent, rel, W1, b1, W2, out);
    cudaEventRecord(evJoin, s2);

    neg_kernel<<<BATCH, 256>>>(neg, ent, rel);   // overlaps mlp

    // join, then combine
    cudaStreamWaitEvent(0, evJoin, 0);
    final_kernel<<<8, 512>>>(b2, out);
}